// round 5
// baseline (speedup 1.0000x reference)
#include <cuda_runtime.h>
#include <cuda_bf16.h>
#include <math.h>
#include <cstdint>

#define BSZ   4096
#define DIM   768
#define COMPS 16384
#define GRD   128
#define NT2   64        // comps tiles of 256

// ---------------- device scratch ----------------
__device__ float g_T[COMPS * DIM];
__device__ float g_wn[COMPS];
__device__ float g_cnt[COMPS];
__device__ float g_s1[COMPS];
__device__ float g_s[COMPS];
__device__ float g_G[GRD * GRD];
__device__ float g_pmin[BSZ * NT2];
__device__ int   g_pidx[BSZ * NT2];
__device__ int   g_bmu[BSZ];
__device__ __nv_bfloat16 g_Xh[BSZ * DIM];
__device__ __nv_bfloat16 g_Xl[BSZ * DIM];
__device__ __nv_bfloat16 g_Wh[COMPS * DIM];
__device__ __nv_bfloat16 g_Wl[COMPS * DIM];

// ---------------- helpers ----------------
__device__ __forceinline__ uint32_t smem_to_u32(const void* p) {
    uint32_t a;
    asm("{ .reg .u64 t; cvta.to.shared.u64 t, %1; cvt.u32.u64 %0, t; }" : "=r"(a) : "l"(p));
    return a;
}
__device__ __forceinline__ void cp_async16(uint32_t dst, const void* src) {
    asm volatile("cp.async.cg.shared.global [%0], [%1], 16;" :: "r"(dst), "l"(src));
}
__device__ __forceinline__ uint32_t lds32(uint32_t a) {
    uint32_t v;
    asm volatile("ld.shared.b32 %0, [%1];" : "=r"(v) : "r"(a));
    return v;
}
__device__ __forceinline__ void mma_bf16(float* d, const uint32_t* a, const uint32_t* b) {
    asm volatile(
        "mma.sync.aligned.m16n8k16.row.col.f32.bf16.bf16.f32 "
        "{%0,%1,%2,%3}, {%4,%5,%6,%7}, {%8,%9}, {%0,%1,%2,%3};"
        : "+f"(d[0]), "+f"(d[1]), "+f"(d[2]), "+f"(d[3])
        : "r"(a[0]), "r"(a[1]), "r"(a[2]), "r"(a[3]), "r"(b[0]), "r"(b[1]));
}

// ---------------- misc small kernels ----------------
__global__ void zero_kernel() {
    int i = blockIdx.x * blockDim.x + threadIdx.x;
    if (i < COMPS * DIM) g_T[i] = 0.f;
    if (i < COMPS) g_cnt[i] = 0.f;
}

__global__ void wnorm_kernel(const float* __restrict__ W) {
    int row = blockIdx.x * 8 + (threadIdx.x >> 5);
    int lane = threadIdx.x & 31;
    const float* wr = W + (size_t)row * DIM;
    float s = 0.f;
    for (int d = lane; d < DIM; d += 32) { float v = wr[d]; s = fmaf(v, v, s); }
    #pragma unroll
    for (int o = 16; o; o >>= 1) s += __shfl_xor_sync(0xffffffffu, s, o);
    if (lane == 0) g_wn[row] = s;
}

__global__ void gmat_kernel(const int* __restrict__ itp) {
    float decay = 1.f - (float)(*itp) / 1000.f;
    float sig = 64.f * decay;
    int a = blockIdx.x, b = threadIdx.x;
    float d = (float)(a - b);
    g_G[a * GRD + b] = expf(-(d * d) / (sig * sig));
}

// fp32 -> (bf16 hi, bf16 lo) split
__global__ void split_kernel(const float* __restrict__ src, __nv_bfloat16* __restrict__ dh,
                             __nv_bfloat16* __restrict__ dl, int n4) {
    int i = blockIdx.x * blockDim.x + threadIdx.x;
    if (i >= n4) return;
    float4 v = *(const float4*)(src + i * 4);
    float x[4] = {v.x, v.y, v.z, v.w};
    ushort4 hh, ll;
    unsigned short* hp = &hh.x; unsigned short* lp = &ll.x;
    #pragma unroll
    for (int k = 0; k < 4; k++) {
        __nv_bfloat16 h = __float2bfloat16(x[k]);
        __nv_bfloat16 l = __float2bfloat16(x[k] - __bfloat162float(h));
        hp[k] = __bfloat16_as_ushort(h);
        lp[k] = __bfloat16_as_ushort(l);
    }
    *(ushort4*)(dh + (size_t)i * 4) = hh;
    *(ushort4*)(dl + (size_t)i * 4) = ll;
}

// ---------------- BMU GEMM via mma.sync bf16 (3-GEMM hi/lo split) --------
// CTA tile: 128(X rows) x 256(W rows), K chunks of 32, double-buffered.
// 8 warps in 2(m) x 4(n): warp tile 64 x 64.
// Stage layout (pitch 40 halfs = 80B per 32-half row):
//   Ah 10240 | Al 10240 | Bh 20480 | Bl 20480  = 61440 B
// Two stages = 122880; wns @122880 (1024B); red_v @123904; red_i @125952.
#define A_TILE_B  10240
#define B_TILE_B  20480
#define STAGE_B   61440
#define WNS_OFF   122880
#define REDV_OFF  123904
#define REDI_OFF  125952
#define BMU_SMEM  128000

__global__ __launch_bounds__(256, 1) void bmu_mma_kernel() {
    extern __shared__ char sm[];
    const uint32_t sb = smem_to_u32(sm);
    const int t = threadIdx.x, lane = t & 31, w = t >> 5;
    const int wm = w >> 2, wn_ = w & 3;
    const int bx = blockIdx.x, by = blockIdx.y;
    const int rowX = by * 128, rowW = bx * 256;

    float* wns   = (float*)(sm + WNS_OFF);
    float* red_v = (float*)(sm + REDV_OFF);
    int*   red_i = (int*)(sm + REDI_OFF);
    wns[t] = g_wn[rowW + t];

    float acc[4][8][4];
    #pragma unroll
    for (int mi = 0; mi < 4; mi++)
        #pragma unroll
        for (int ni = 0; ni < 8; ni++)
            #pragma unroll
            for (int k = 0; k < 4; k++) acc[mi][ni][k] = 0.f;

    // loader: A tiles 512 uint4 (2/thread), B tiles 1024 uint4 (4/thread)
    auto load_stage = [&](int s, int c) {
        uint32_t base = sb + s * STAGE_B;
        #pragma unroll
        for (int i = 0; i < 2; i++) {
            int idx = t + i * 256;
            int r = idx >> 2, g = idx & 3;
            uint32_t so = (uint32_t)(r * 80 + g * 16);
            size_t go = (size_t)(rowX + r) * DIM + c * 32 + g * 8;
            cp_async16(base + so,            g_Xh + go);
            cp_async16(base + A_TILE_B + so, g_Xl + go);
        }
        #pragma unroll
        for (int i = 0; i < 4; i++) {
            int idx = t + i * 256;
            int r = idx >> 2, g = idx & 3;
            uint32_t so = (uint32_t)(r * 80 + g * 16);
            size_t go = (size_t)(rowW + r) * DIM + c * 32 + g * 8;
            cp_async16(base + 2 * A_TILE_B + so,            g_Wh + go);
            cp_async16(base + 2 * A_TILE_B + B_TILE_B + so, g_Wl + go);
        }
    };

    const int arow = lane >> 2, acol = (lane & 3) * 2;

    auto compute = [&](int s, int kk) {
        uint32_t Ah = sb + s * STAGE_B;
        uint32_t Al = Ah + A_TILE_B;
        uint32_t Bh = Ah + 2 * A_TILE_B;
        uint32_t Bl = Bh + B_TILE_B;

        uint32_t bh[8][2], bl[8][2];
        #pragma unroll
        for (int ni = 0; ni < 8; ni++) {
            uint32_t off = (uint32_t)(((wn_ * 64 + ni * 8 + arow) * 40 + kk + acol) * 2);
            bh[ni][0] = lds32(Bh + off); bh[ni][1] = lds32(Bh + off + 16);
            bl[ni][0] = lds32(Bl + off); bl[ni][1] = lds32(Bl + off + 16);
        }
        uint32_t a[4][4];
        #pragma unroll
        for (int mi = 0; mi < 4; mi++) {
            uint32_t off = (uint32_t)(((wm * 64 + mi * 16 + arow) * 40 + kk + acol) * 2);
            a[mi][0] = lds32(Ah + off);      a[mi][1] = lds32(Ah + off + 640);
            a[mi][2] = lds32(Ah + off + 16); a[mi][3] = lds32(Ah + off + 656);
        }
        #pragma unroll
        for (int mi = 0; mi < 4; mi++)
            #pragma unroll
            for (int ni = 0; ni < 8; ni++) mma_bf16(acc[mi][ni], a[mi], bh[ni]);
        #pragma unroll
        for (int mi = 0; mi < 4; mi++)
            #pragma unroll
            for (int ni = 0; ni < 8; ni++) mma_bf16(acc[mi][ni], a[mi], bl[ni]);
        #pragma unroll
        for (int mi = 0; mi < 4; mi++) {
            uint32_t off = (uint32_t)(((wm * 64 + mi * 16 + arow) * 40 + kk + acol) * 2);
            a[mi][0] = lds32(Al + off);      a[mi][1] = lds32(Al + off + 640);
            a[mi][2] = lds32(Al + off + 16); a[mi][3] = lds32(Al + off + 656);
        }
        #pragma unroll
        for (int mi = 0; mi < 4; mi++)
            #pragma unroll
            for (int ni = 0; ni < 8; ni++) mma_bf16(acc[mi][ni], a[mi], bh[ni]);
    };

    load_stage(0, 0);
    asm volatile("cp.async.commit_group;");
    for (int c = 0; c < 24; c++) {
        if (c < 23) {
            load_stage((c + 1) & 1, c + 1);
            asm volatile("cp.async.commit_group;");
            asm volatile("cp.async.wait_group 1;");
        } else {
            asm volatile("cp.async.wait_group 0;");
        }
        __syncthreads();
        compute(c & 1, 0);
        compute(c & 1, 16);
        __syncthreads();
    }

    // epilogue: d2 = wn - 2*dot, per-row argmin over 256 cols
    #pragma unroll
    for (int mi = 0; mi < 4; mi++) {
        #pragma unroll
        for (int h = 0; h < 2; h++) {
            float bv = 3.4e38f; int bi = 0x7fffffff;
            #pragma unroll
            for (int ni = 0; ni < 8; ni++) {
                #pragma unroll
                for (int cc = 0; cc < 2; cc++) {
                    int nl = wn_ * 64 + ni * 8 + (lane & 3) * 2 + cc;
                    float d2 = wns[nl] - 2.f * acc[mi][ni][h * 2 + cc];
                    if (d2 < bv) { bv = d2; bi = rowW + nl; }
                }
            }
            #pragma unroll
            for (int o = 1; o < 4; o <<= 1) {
                float ov = __shfl_xor_sync(0xffffffffu, bv, o);
                int   oi = __shfl_xor_sync(0xffffffffu, bi, o);
                if (ov < bv || (ov == bv && oi < bi)) { bv = ov; bi = oi; }
            }
            if ((lane & 3) == 0) {
                int rl = wm * 64 + mi * 16 + arow + h * 8;
                red_v[rl * 4 + wn_] = bv;
                red_i[rl * 4 + wn_] = bi;
            }
        }
    }
    __syncthreads();
    if (t < 128) {
        float bv = red_v[t * 4]; int bi = red_i[t * 4];
        #pragma unroll
        for (int j = 1; j < 4; j++) {
            float v = red_v[t * 4 + j]; int ii = red_i[t * 4 + j];
            if (v < bv || (v == bv && ii < bi)) { bv = v; bi = ii; }
        }
        g_pmin[(size_t)(rowX + t) * NT2 + bx] = bv;
        g_pidx[(size_t)(rowX + t) * NT2 + bx] = bi;
    }
}

// ---------------- reduce 64 partials per batch row ----------------
__global__ void bmu_reduce_kernel() {
    __shared__ float sv[64];
    __shared__ int   si[64];
    int b = blockIdx.x, t = threadIdx.x;
    sv[t] = g_pmin[(size_t)b * NT2 + t];
    si[t] = g_pidx[(size_t)b * NT2 + t];
    __syncthreads();
    for (int s = 32; s; s >>= 1) {
        if (t < s) {
            float v = sv[t + s]; int ii = si[t + s];
            if (v < sv[t] || (v == sv[t] && ii < si[t])) { sv[t] = v; si[t] = ii; }
        }
        __syncthreads();
    }
    if (t == 0) g_bmu[b] = si[0];
}

__global__ void scatter_kernel(const float* __restrict__ X) {
    int b = blockIdx.x;
    int u = g_bmu[b];
    const float* xr = X + (size_t)b * DIM;
    float* tr = g_T + (size_t)u * DIM;
    for (int d = threadIdx.x; d < DIM; d += blockDim.x)
        atomicAdd(&tr[d], xr[d]);
    if (threadIdx.x == 0) atomicAdd(&g_cnt[u], 1.f);
}

// ---------------- separable Gaussian conv (128-matmul), in place ----------
__global__ __launch_bounds__(256) void conv_kernel(int rstride) {
    __shared__ float Ts[16][64];
    __shared__ float Gs[16][128];
    int t = threadIdx.x;
    size_t base = (size_t)blockIdx.y * (GRD * DIM) + (size_t)blockIdx.x * 64;
    int cg = t & 15, rg = t >> 4;
    int lk = t >> 4, lc = (t & 15) * 4, gi = (t & 15) * 8;

    float acc[8][4];
    #pragma unroll
    for (int r = 0; r < 8; r++)
        #pragma unroll
        for (int c = 0; c < 4; c++) acc[r][c] = 0.f;

    for (int k0 = 0; k0 < GRD; k0 += 16) {
        if (k0) __syncthreads();
        *(float4*)&Ts[lk][lc]     = *(const float4*)&g_T[base + (size_t)(k0 + lk) * rstride + lc];
        *(float4*)&Gs[lk][gi]     = *(const float4*)&g_G[(k0 + lk) * GRD + gi];
        *(float4*)&Gs[lk][gi + 4] = *(const float4*)&g_G[(k0 + lk) * GRD + gi + 4];
        __syncthreads();
        #pragma unroll
        for (int k = 0; k < 16; k++) {
            float4 tv = *(const float4*)&Ts[k][cg * 4];
            float tc[4] = {tv.x, tv.y, tv.z, tv.w};
            #pragma unroll
            for (int r = 0; r < 8; r++) {
                float g = Gs[k][rg * 8 + r];
                #pragma unroll
                for (int c = 0; c < 4; c++)
                    acc[r][c] = fmaf(g, tc[c], acc[r][c]);
            }
        }
    }
    #pragma unroll
    for (int r = 0; r < 8; r++) {
        float4 o = make_float4(acc[r][0], acc[r][1], acc[r][2], acc[r][3]);
        *(float4*)&g_T[base + (size_t)(rg * 8 + r) * rstride + cg * 4] = o;
    }
}

__global__ void convs1_kernel() {
    int ip = blockIdx.x, j = threadIdx.x;
    float s = 0.f;
    for (int i = 0; i < GRD; i++)
        s = fmaf(g_G[ip * GRD + i], g_cnt[i * GRD + j], s);
    g_s1[ip * GRD + j] = s;
}
__global__ void convs2_kernel() {
    int i = blockIdx.x, jp = threadIdx.x;
    float s = 0.f;
    for (int j = 0; j < GRD; j++)
        s = fmaf(g_G[j * GRD + jp], g_s1[i * GRD + j], s);
    g_s[i * GRD + jp] = s;
}

__global__ void final_kernel(const float* __restrict__ W, float* __restrict__ out,
                             const int* __restrict__ itp) {
    float decay = 1.f - (float)(*itp) / 1000.f;
    float alpha = 0.3f * decay;
    int idx = blockIdx.x * blockDim.x + threadIdx.x;
    int i4 = idx * 4;
    if (i4 >= COMPS * DIM) return;
    int c = i4 / DIM;
    float m = 1.f - alpha * g_s[c];
    float4 w = *(const float4*)(W + i4);
    float4 v = *(const float4*)(g_T + i4);
    float4 o = make_float4(w.x * m + alpha * v.x, w.y * m + alpha * v.y,
                           w.z * m + alpha * v.z, w.w * m + alpha * v.w);
    *(float4*)(out + i4) = o;
}

// ---------------- launch ----------------
extern "C" void kernel_launch(void* const* d_in, const int* in_sizes, int n_in,
                              void* d_out, int out_size) {
    const float* X   = (const float*)d_in[0];
    const float* W   = (const float*)d_in[1];
    const int*   itp = (const int*)d_in[2];
    float* out = (float*)d_out;

    cudaFuncSetAttribute(bmu_mma_kernel, cudaFuncAttributeMaxDynamicSharedMemorySize, BMU_SMEM);

    __nv_bfloat16 *xh, *xl, *wh, *wl;
    cudaGetSymbolAddress((void**)&xh, g_Xh);
    cudaGetSymbolAddress((void**)&xl, g_Xl);
    cudaGetSymbolAddress((void**)&wh, g_Wh);
    cudaGetSymbolAddress((void**)&wl, g_Wl);

    zero_kernel<<<(COMPS * DIM + 255) / 256, 256>>>();
    wnorm_kernel<<<COMPS / 8, 256>>>(W);
    gmat_kernel<<<GRD, GRD>>>(itp);
    split_kernel<<<(BSZ * DIM / 4 + 255) / 256, 256>>>(X, xh, xl, BSZ * DIM / 4);
    split_kernel<<<(COMPS * DIM / 4 + 255) / 256, 256>>>(W, wh, wl, COMPS * DIM / 4);

    bmu_mma_kernel<<<dim3(NT2, BSZ / 128), 256, BMU_SMEM>>>();
    bmu_reduce_kernel<<<BSZ, 64>>>();
    scatter_kernel<<<BSZ, 256>>>(X);

    conv_kernel<<<dim3(GRD * DIM / 64, 1), 256>>>(GRD * DIM);
    conv_kernel<<<dim3(DIM / 64, GRD), 256>>>(DIM);
    convs1_kernel<<<GRD, GRD>>>();
    convs2_kernel<<<GRD, GRD>>>();

    final_kernel<<<(COMPS * DIM / 4 + 255) / 256, 256>>>(W, out, itp);
}